// round 13
// baseline (speedup 1.0000x reference)
#include <cuda_runtime.h>
#include <cstdint>

// Problem constants (D=20, RANK=2 -> o=19 per axis, m=32)
#define O      19
#define DM     20
#define MM     32
#define ROWP   36                    // padded row (floats) -> conflict-free LDS.128
#define CT_STRIDE (MM*ROWP)          // 1152 floats per cos-table slab
#define NT     640                   // 20 warps: (c-pair 0..9) x (d-group 0..1)
#define NITEMS (O*O*2)               // (a,b) x d-half

typedef unsigned long long ull;

// ---- packed f32x2 helpers ----
__device__ __forceinline__ ull f2mul(ull a, ull b) {
    ull r; asm("mul.rn.f32x2 %0, %1, %2;" : "=l"(r) : "l"(a), "l"(b)); return r;
}
__device__ __forceinline__ ull f2fma(ull a, ull b, ull c) {
    ull r; asm("fma.rn.f32x2 %0, %1, %2, %3;" : "=l"(r) : "l"(a), "l"(b), "l"(c)); return r;
}
__device__ __forceinline__ float f2sum(ull v) {
    return __uint_as_float((unsigned)v) + __uint_as_float((unsigned)(v >> 32));
}

// Shared memory layout (floats):
//   Ct  [19][32][36]    @ 0      (21888)  cos table
//   R   [2][20][20][32] @ 21888  (25600)  double-buffered (a,b)-pair sums
//   Gab [2][32][36]     @ 47488  (2304)   double-buffered P*Ct[A]*Ct[B]
//   Msc [32][36]        @ 49792  (1152)   M_w / 16
//   X   [20][2][5][32]  @ 50944  (6400)   per-warp private ws/x slots
#define CT_OFF   0
#define R_OFF    21888
#define RBUF     12800
#define GAB_OFF  47488
#define GBUF     1152
#define MS_OFF   49792
#define X_OFF    50944
#define SMEM_FLOATS 57344
#define SMEM_BYTES (SMEM_FLOATS * 4)   // 229376 B <= 232448 B opt-in max

// ---- cooperative stage: R[buf] = 2x2 (a,b) pair-sum; Gab[buf] = P*Ct[A]*Ct[B] ----
__device__ __forceinline__ void stage_item(const float* __restrict__ H,
                                           const float* __restrict__ P,
                                           float* __restrict__ s,
                                           int it, int tid, int buf)
{
    const int ab = it >> 1;
    const int A = ab / O;
    const int B = ab % O;
    float* R   = s + R_OFF + buf * RBUF;
    float* Gab = s + GAB_OFF + buf * GBUF;
    float* Ct  = s + CT_OFF;

    const int strideB = DM * DM * MM;        // 12800 floats
    const int strideA = DM * strideB;
    const float4* H00 = (const float4*)(H + (long)A * strideA + (long)B * strideB);
    const float4* H01 = H00 + strideB / 4;
    const float4* H10 = H00 + strideA / 4;
    const float4* H11 = H10 + strideB / 4;
    float4* R4 = (float4*)R;

    float4 pa[5], pb[5], acc[5];
    #pragma unroll
    for (int k = 0; k < 5; k++) { pa[k] = H00[tid + k * NT]; pb[k] = H01[tid + k * NT]; }
    #pragma unroll
    for (int k = 0; k < 5; k++) {
        acc[k] = make_float4(pa[k].x + pb[k].x, pa[k].y + pb[k].y,
                             pa[k].z + pb[k].z, pa[k].w + pb[k].w);
    }
    #pragma unroll
    for (int k = 0; k < 5; k++) { pa[k] = H10[tid + k * NT]; pb[k] = H11[tid + k * NT]; }
    #pragma unroll
    for (int k = 0; k < 5; k++) {
        R4[tid + k * NT] = make_float4(acc[k].x + pa[k].x + pb[k].x,
                                       acc[k].y + pa[k].y + pb[k].y,
                                       acc[k].z + pa[k].z + pb[k].z,
                                       acc[k].w + pa[k].w + pb[k].w);
    }

    for (int e = tid; e < MM * MM; e += NT) {
        int i = e >> 5, j = e & 31;
        Gab[i * ROWP + j] = P[e] * Ct[A * CT_STRIDE + i * ROWP + j]
                                 * Ct[B * CT_STRIDE + i * ROWP + j];
    }
}

__global__ void __launch_bounds__(NT, 1)
pm4_kernel(const float* __restrict__ H,   // [20,20,20,20,32]
           const float* __restrict__ Mw,  // [32,32]
           const float* __restrict__ P,   // [32,32]
           float* __restrict__ out)       // [19^4, 32]
{
    extern __shared__ float s[];
    float* Ct  = s + CT_OFF;
    float* Msc = s + MS_OFF;

    const int tid  = threadIdx.x;
    const int lane = tid & 31;
    const int w    = tid >> 5;
    const int cp   = w >> 1;          // 0..9
    const int dg   = w & 1;           // 0..1
    const int c0   = 2 * cp;
    const int nc   = (cp == 9) ? 1 : 2;
    const int c1   = (nc == 2) ? c0 + 1 : c0;
    const int g    = gridDim.x;

    float* Xw0 = s + X_OFF + w * 320;     // 5 slots x 32 (c0-side)
    float* Xw1 = Xw0 + 160;               // 5 slots x 32 (c1-side)

    const float TWO_PI = 6.28318530717958647692f;

    // ---- once per CTA: cos table + prescaled M ----
    for (int e = tid; e < O * MM * MM; e += NT) {
        int n = e >> 10;
        int r = e & 1023;
        int i = r >> 5;
        int j = r & 31;
        float per = (float)(i * MM + j + 2);
        Ct[n * CT_STRIDE + i * ROWP + j] = cosf(TWO_PI * (float)n / per);
    }
    for (int e = tid; e < MM * MM; e += NT) {
        Msc[(e >> 5) * ROWP + (e & 31)] = Mw[e] * 0.0625f;
    }
    __syncthreads();   // Ct ready for stage_item

    // ---- prologue: stage first item into buf 0 ----
    if (blockIdx.x < NITEMS)
        stage_item(H, P, s, blockIdx.x, tid, 0);
    __syncthreads();

    int buf = 0;
    for (int item = blockIdx.x; item < NITEMS; item += g, buf ^= 1) {
        const int ab = item >> 1;
        const int dh = item & 1;
        const int dstart = dh ? 10 : 0;
        const int dnum   = dh ? 9 : 10;
        const int cnt    = (dnum - dg + 1) >> 1;   // this warp's dd count (4 or 5)
        const float* Rb  = s + R_OFF + buf * RBUF;
        const float* Gb  = s + GAB_OFF + buf * GBUF;

        // ---- Phase P-a: this warp's window sums -> private slots (no sync) ----
        #pragma unroll 1
        for (int t = 0; t < cnt; t++) {
            const int d = dstart + dg + 2 * t;
            const float* r0 = &Rb[(c0 * DM + d) * MM + lane];
            float rA = r0[0]            + r0[MM];
            float rB = r0[DM * MM]      + r0[DM * MM + MM];
            Xw0[t * 32 + lane] = rA + rB;
            if (nc == 2) {
                float rC = r0[2 * DM * MM] + r0[2 * DM * MM + MM];
                Xw1[t * 32 + lane] = rB + rC;
            }
        }
        __syncwarp();

        // ---- Phase P-b: matvec per slot (broadcast reads, overwrite in place) ----
        {
            ull Mreg[16];
            #pragma unroll
            for (int l4 = 0; l4 < 8; l4++) {
                ulonglong2 m = *reinterpret_cast<const ulonglong2*>(&Msc[lane * ROWP + 4 * l4]);
                Mreg[2 * l4] = m.x; Mreg[2 * l4 + 1] = m.y;
            }
            #pragma unroll 1
            for (int t = 0; t < cnt; t++) {
                ull a0 = 0, a0b = 0, a1 = 0, a1b = 0;
                #pragma unroll
                for (int l4 = 0; l4 < 8; l4++) {
                    ulonglong2 w0 = *reinterpret_cast<const ulonglong2*>(&Xw0[t * 32 + 4 * l4]);
                    a0  = f2fma(Mreg[2 * l4],     w0.x, a0);
                    a0b = f2fma(Mreg[2 * l4 + 1], w0.y, a0b);
                    if (nc == 2) {
                        ulonglong2 w1 = *reinterpret_cast<const ulonglong2*>(&Xw1[t * 32 + 4 * l4]);
                        a1  = f2fma(Mreg[2 * l4],     w1.x, a1);
                        a1b = f2fma(Mreg[2 * l4 + 1], w1.y, a1b);
                    }
                }
                Xw0[t * 32 + lane] = f2sum(a0) + f2sum(a0b);
                if (nc == 2) Xw1[t * 32 + lane] = f2sum(a1) + f2sum(a1b);
            }
        }

        // ---- per-warp G = Gab * Ct[c] ----
        ull G0[16], G1[16];
        #pragma unroll
        for (int l4 = 0; l4 < 8; l4++) {
            ulonglong2 gv = *reinterpret_cast<const ulonglong2*>(&Gb[lane * ROWP + 4 * l4]);
            ulonglong2 ca = *reinterpret_cast<const ulonglong2*>(&Ct[c0 * CT_STRIDE + lane * ROWP + 4 * l4]);
            ulonglong2 cb = *reinterpret_cast<const ulonglong2*>(&Ct[c1 * CT_STRIDE + lane * ROWP + 4 * l4]);
            G0[2 * l4]     = f2mul(gv.x, ca.x);
            G0[2 * l4 + 1] = f2mul(gv.y, ca.y);
            G1[2 * l4]     = f2mul(gv.x, cb.x);
            G1[2 * l4 + 1] = f2mul(gv.y, cb.y);
        }
        __syncwarp();   // x slots visible across lanes

        // ---- Phase C: same warp consumes its own x slots (staggered order) ----
        {
            const int outBase = ab * (O * O) * MM;
            int it0 = cp % cnt;
            #pragma unroll 1
            for (int tt = 0; tt < cnt; tt++) {
                int t = it0 + tt; if (t >= cnt) t -= cnt;
                const int d = dstart + dg + 2 * t;
                const float* cdrow = &Ct[d * CT_STRIDE + lane * ROWP];
                const float* xv0p  = &Xw0[t * 32];
                const float* xv1p  = &Xw1[t * 32];
                ull A0 = 0, A0b = 0, A1 = 0, A1b = 0;
                #pragma unroll
                for (int l4 = 0; l4 < 8; l4++) {
                    ulonglong2 cd  = *reinterpret_cast<const ulonglong2*>(cdrow + 4 * l4);
                    ulonglong2 xv0 = *reinterpret_cast<const ulonglong2*>(xv0p + 4 * l4);
                    ulonglong2 xv1 = *reinterpret_cast<const ulonglong2*>(xv1p + 4 * l4);
                    A0  = f2fma(f2mul(cd.x, G0[2 * l4]),     xv0.x, A0);
                    A0b = f2fma(f2mul(cd.y, G0[2 * l4 + 1]), xv0.y, A0b);
                    A1  = f2fma(f2mul(cd.x, G1[2 * l4]),     xv1.x, A1);
                    A1b = f2fma(f2mul(cd.y, G1[2 * l4 + 1]), xv1.y, A1b);
                }
                out[outBase + (c0 * O + d) * MM + lane] = f2sum(A0) + f2sum(A0b);
                if (nc == 2)
                    out[outBase + (c1 * O + d) * MM + lane] = f2sum(A1) + f2sum(A1b);
            }
        }

        // ---- tail: stage next item into the other buffer (overlaps phase C) ----
        if (item + g < NITEMS)
            stage_item(H, P, s, item + g, tid, buf ^ 1);

        __syncthreads();   // the single per-item barrier
    }
}

extern "C" void kernel_launch(void* const* d_in, const int* in_sizes, int n_in,
                              void* d_out, int out_size)
{
    const float* H  = (const float*)d_in[0];
    const float* Mw = (const float*)d_in[1];
    const float* P  = (const float*)d_in[2];
    float* out = (float*)d_out;

    cudaFuncSetAttribute(pm4_kernel, cudaFuncAttributeMaxDynamicSharedMemorySize, SMEM_BYTES);

    int dev = 0, nsm = 148;
    cudaGetDevice(&dev);
    cudaDeviceGetAttribute(&nsm, cudaDevAttrMultiProcessorCount, dev);
    if (nsm <= 0) nsm = 148;
    int grid = nsm > NITEMS ? NITEMS : nsm;

    pm4_kernel<<<grid, NT, SMEM_BYTES>>>(H, Mw, P, out);
}